// round 5
// baseline (speedup 1.0000x reference)
#include <cuda_runtime.h>
#include <cuda_fp16.h>
#include <cstdint>

#define BB 8
#define NN 1024
#define CC 256
#define HH 8
#define HD 32
#define TABLE 10

// Scratch (allocation-free rule: __device__ globals)
__device__ __half g_ah [BB*NN*CC];      // X in fp16, row-major [8192][256]
__device__ __half g_wqt[3*CC*CC];       // W_qkv^T fp16 [768][256]
__device__ __half g_wpt[CC*CC];         // W_proj^T fp16 [256][256]
__device__ __half g_qh [BB*HH*NN*HD];   // pre-scaled q, fp16
__device__ __half g_kh [BB*HH*NN*HD];
__device__ __half g_vh [BB*HH*NN*HD];
__device__ __half g_xh [BB*NN*CC];      // attention output fp16 [8192][256]

// ---------------------------------------------------------------------------
// helpers
// ---------------------------------------------------------------------------
__device__ __forceinline__ void mma_f16(float* c, const uint32_t* a, const uint32_t* b) {
    asm volatile(
        "mma.sync.aligned.m16n8k16.row.col.f32.f16.f16.f32 "
        "{%0,%1,%2,%3},{%4,%5,%6,%7},{%8,%9},{%0,%1,%2,%3};\n"
        : "+f"(c[0]), "+f"(c[1]), "+f"(c[2]), "+f"(c[3])
        : "r"(a[0]), "r"(a[1]), "r"(a[2]), "r"(a[3]), "r"(b[0]), "r"(b[1]));
}
__device__ __forceinline__ void ldsm4(uint32_t* r, uint32_t addr) {
    asm volatile("ldmatrix.sync.aligned.m8n8.x4.shared.b16 {%0,%1,%2,%3},[%4];"
                 : "=r"(r[0]), "=r"(r[1]), "=r"(r[2]), "=r"(r[3]) : "r"(addr));
}
__device__ __forceinline__ uint32_t smem_u32(const void* p) {
    uint32_t a;
    asm("{ .reg .u64 t; cvta.to.shared.u64 t, %1; cvt.u32.u64 %0, t; }" : "=r"(a) : "l"(p));
    return a;
}
__device__ __forceinline__ void cp16(uint32_t dst, const void* src) {
    asm volatile("cp.async.ca.shared.global [%0],[%1],16;" :: "r"(dst), "l"(src));
}
__device__ __forceinline__ void cp_commit() { asm volatile("cp.async.commit_group;"); }
__device__ __forceinline__ void cp_wait0()  { asm volatile("cp.async.wait_group 0;"); }
__device__ __forceinline__ uint32_t h2pack(float lo, float hi) {
    __half2 h = __floats2half2_rn(lo, hi);
    return *(uint32_t*)&h;
}
__device__ __forceinline__ uint32_t prmt(uint32_t a, uint32_t b, uint32_t s) {
    uint32_t d;
    asm("prmt.b32 %0,%1,%2,%3;" : "=r"(d) : "r"(a), "r"(b), "r"(s));
    return d;
}

// ---------------------------------------------------------------------------
// Conversions
// ---------------------------------------------------------------------------
__global__ void __launch_bounds__(256) convert_x_kernel(const float4* __restrict__ X,
                                                        uint4* __restrict__ out)
{
    int idx = blockIdx.x * 256 + threadIdx.x;   // 8 floats each
    float4 a = X[idx * 2], b = X[idx * 2 + 1];
    __half2 h0 = __floats2half2_rn(a.x, a.y);
    __half2 h1 = __floats2half2_rn(a.z, a.w);
    __half2 h2 = __floats2half2_rn(b.x, b.y);
    __half2 h3 = __floats2half2_rn(b.z, b.w);
    out[idx] = make_uint4(*(uint32_t*)&h0, *(uint32_t*)&h1,
                          *(uint32_t*)&h2, *(uint32_t*)&h3);
}

// W [256][N] fp32 -> Wt [N][256] fp16
__global__ void __launch_bounds__(256) transpose_w_kernel(const float* __restrict__ W,
                                                          __half* __restrict__ Wt, int N)
{
    __shared__ float tile[32][33];
    int n0 = blockIdx.x * 32, k0 = blockIdx.y * 32;
    int tx = threadIdx.x & 31, ty = threadIdx.x >> 5;
    #pragma unroll
    for (int i = 0; i < 4; i++)
        tile[ty + i * 8][tx] = W[(k0 + ty + i * 8) * N + n0 + tx];
    __syncthreads();
    #pragma unroll
    for (int i = 0; i < 4; i++)
        Wt[(n0 + ty + i * 8) * 256 + k0 + tx] = __float2half_rn(tile[tx][ty + i * 8]);
}

// ---------------------------------------------------------------------------
// fp16 tensor-core GEMM: C[M,N] = A[M,256] @ Wt[N,256]^T
// block 128x128, K-chunks of 64, cp.async double buffer.
// PROJ=false: scatter to g_qh(scaled)/g_kh/g_vh.  PROJ=true: out = C + bias (fp32)
// ---------------------------------------------------------------------------
#define GS_ROW 9     // uint4 per smem row (8 data + 1 pad): LDSM conflict-free
#define GS_TILE (128 * GS_ROW)   // 1152 uint4 per tile
#define GS_BUF  (2 * GS_TILE)    // A + B per buffer

template<bool PROJ>
__global__ void __launch_bounds__(256) gemm_f16_kernel(
    const uint4* __restrict__ A4, const uint4* __restrict__ B4,
    float* __restrict__ outp, const float* __restrict__ bias)
{
    extern __shared__ uint4 smem4[];
    const int tid  = threadIdx.x;
    const int warp = tid >> 5, lane = tid & 31;
    const int g = lane >> 2, t = lane & 3;
    const int m0 = blockIdx.y * 128, n0 = blockIdx.x * 128;
    const int wm = warp >> 2, wn = warp & 3;    // 2x4 warps: 64 rows x 32 cols
    const uint32_t sb = smem_u32(smem4);
    const int arow = lane & 15, chi = lane >> 4;

    float acc[4][4][4];
    #pragma unroll
    for (int mt = 0; mt < 4; mt++)
        #pragma unroll
        for (int nt = 0; nt < 4; nt++)
            #pragma unroll
            for (int r = 0; r < 4; r++) acc[mt][nt][r] = 0.f;

    // async-load chunk c into buffer buf
    auto load_chunk = [&](int c, int buf) {
        #pragma unroll
        for (int i = 0; i < 4; i++) {
            int idx = i * 256 + tid;           // 1024 uint4 per tile
            int row = idx >> 3, cc = idx & 7;
            uint32_t da = sb + (uint32_t)(buf * GS_BUF + row * GS_ROW + cc) * 16;
            cp16(da, &A4[(long)(m0 + row) * 32 + c * 8 + cc]);
            uint32_t db = sb + (uint32_t)(buf * GS_BUF + GS_TILE + row * GS_ROW + cc) * 16;
            cp16(db, &B4[(long)(n0 + row) * 32 + c * 8 + cc]);
        }
        cp_commit();
    };

    load_chunk(0, 0);

    for (int c = 0; c < 4; c++) {
        cp_wait0();
        __syncthreads();
        if (c < 3) load_chunk(c + 1, (c + 1) & 1);
        const int bo = (c & 1) * GS_BUF;

        #pragma unroll
        for (int ks = 0; ks < 4; ks++) {
            uint32_t af[4][4];
            #pragma unroll
            for (int mt = 0; mt < 4; mt++)
                ldsm4(af[mt], sb + (uint32_t)(bo + (wm * 64 + mt * 16 + arow) * GS_ROW
                                              + ks * 2 + chi) * 16);
            uint32_t bf[2][4];
            #pragma unroll
            for (int np = 0; np < 2; np++)
                ldsm4(bf[np], sb + (uint32_t)(bo + GS_TILE
                                              + (wn * 32 + np * 16 + arow) * GS_ROW
                                              + ks * 2 + chi) * 16);
            #pragma unroll
            for (int mt = 0; mt < 4; mt++)
                #pragma unroll
                for (int nt = 0; nt < 4; nt++) {
                    uint32_t bb[2] = { bf[nt >> 1][nt & 1], bf[nt >> 1][(nt & 1) + 2] };
                    mma_f16(acc[mt][nt], af[mt], bb);
                }
        }
        __syncthreads();
    }

    if (PROJ) {
        #pragma unroll
        for (int mt = 0; mt < 4; mt++) {
            int m = m0 + wm * 64 + mt * 16 + g;
            #pragma unroll
            for (int nt = 0; nt < 4; nt++) {
                int col = n0 + wn * 32 + nt * 8 + 2 * t;
                float b0 = bias[col], b1 = bias[col + 1];
                *(float2*)&outp[(long)m * 256 + col] =
                    make_float2(acc[mt][nt][0] + b0, acc[mt][nt][1] + b1);
                *(float2*)&outp[(long)(m + 8) * 256 + col] =
                    make_float2(acc[mt][nt][2] + b0, acc[mt][nt][3] + b1);
            }
        }
    } else {
        const float scale = 0.17677669529663687f;   // 32^-0.5 folded into q
        #pragma unroll
        for (int mt = 0; mt < 4; mt++) {
            int m = m0 + wm * 64 + mt * 16 + g;
            int bb = m >> 10, nn = m & 1023;
            #pragma unroll
            for (int nt = 0; nt < 4; nt++) {
                int col = n0 + wn * 32 + nt * 8 + 2 * t;
                int sel = col >> 8, hh = (col >> 5) & 7, dd = col & 31;
                float c0 = acc[mt][nt][0], c1 = acc[mt][nt][1];
                float c2 = acc[mt][nt][2], c3 = acc[mt][nt][3];
                if (sel == 0) { c0 *= scale; c1 *= scale; c2 *= scale; c3 *= scale; }
                __half* dst = (sel == 0) ? g_qh : (sel == 1) ? g_kh : g_vh;
                long base = (((long)bb * HH + hh) * NN + nn) * HD + dd;
                *(__half2*)&dst[base]           = __floats2half2_rn(c0, c1);
                *(__half2*)&dst[base + 8 * HD]  = __floats2half2_rn(c2, c3);
            }
        }
    }
}

// ---------------------------------------------------------------------------
// Fused flash attention, fp16 mma.m16n8k16 (unchanged core from R3),
// epilogue now writes fp16 g_xh.
// ---------------------------------------------------------------------------
#define KP_STRIDE 40

__global__ void __launch_bounds__(256, 2) attn_mma_kernel(
    const int* __restrict__ rp, const int* __restrict__ rel_len,
    const float* __restrict__ bias_table)
{
    extern __shared__ uint32_t sm[];
    uint32_t* kp_s = sm;
    uint32_t* vp_s = kp_s + 8 * 16 * KP_STRIDE;
    int*      rp_s = (int*)(vp_s + 8 * 16 * KP_STRIDE);

    const int tid  = threadIdx.x;
    const int h    = tid >> 5;
    const int lane = tid & 31;
    const int g    = lane >> 2;
    const int t    = lane & 3;
    const int b    = blockIdx.x >> 5;
    const int row0 = (blockIdx.x & 31) * 32;

    const int mask_len = (int)(__int2float_rn(rel_len[b]) * 0.5f);
    float bt2 = 0.f;
    if (lane < TABLE)
        bt2 = bias_table[lane * HH + h] + ((lane > mask_len) ? -100.f : 0.f);

    uint32_t qa[2][2][4];
    {
        const uint32_t* qw = (const uint32_t*)g_qh;
        long rbase = ((long)(b * HH) + h) * NN + row0;
        #pragma unroll
        for (int mt = 0; mt < 2; mt++) {
            long rA = (rbase + mt * 16 + g) * 16;
            long rB = rA + 8 * 16;
            #pragma unroll
            for (int ks = 0; ks < 2; ks++) {
                int w = ks * 8 + t;
                qa[mt][ks][0] = qw[rA + w];
                qa[mt][ks][1] = qw[rB + w];
                qa[mt][ks][2] = qw[rA + w + 4];
                qa[mt][ks][3] = qw[rB + w + 4];
            }
        }
    }

    float o[2][4][4];
    #pragma unroll
    for (int mt = 0; mt < 2; mt++)
        #pragma unroll
        for (int nt = 0; nt < 4; nt++)
            #pragma unroll
            for (int r = 0; r < 4; r++) o[mt][nt][r] = 0.f;
    float mrow[2][2] = {{-1e30f, -1e30f}, {-1e30f, -1e30f}};
    float lrow[2][2] = {{0.f, 0.f}, {0.f, 0.f}};

    const uint32_t* kh = &kp_s[h * 16 * KP_STRIDE];
    const uint32_t* vh = &vp_s[h * 16 * KP_STRIDE];
    const __half* gk = g_kh;
    const __half* gv = g_vh;

    for (int j0 = 0; j0 < NN; j0 += 32) {
        __syncthreads();
        #pragma unroll
        for (int it = 0; it < 4; it++) {
            int idx = it * 256 + tid;
            int key = idx & 31;
            int q4  = (idx >> 5) & 3;
            int h2  = idx >> 7;
            long base = (((long)(b * HH + h2)) * NN + j0 + key) * 32;
            uint4 kw = *(const uint4*)(gk + base + q4 * 8);
            uint32_t* col = &kp_s[h2 * (16 * KP_STRIDE) + (q4 * 4) * KP_STRIDE + key];
            col[0 * KP_STRIDE] = kw.x;
            col[1 * KP_STRIDE] = kw.y;
            col[2 * KP_STRIDE] = kw.z;
            col[3 * KP_STRIDE] = kw.w;
        }
        #pragma unroll
        for (int it = 0; it < 2; it++) {
            int idx = it * 256 + tid;
            int d4   = idx & 3;
            int key2 = (idx >> 2) & 15;
            int h2   = idx >> 6;
            long base = (((long)(b * HH + h2)) * NN + j0 + 2 * key2) * 32;
            uint4 v0 = *(const uint4*)(gv + base + d4 * 8);
            uint4 v1 = *(const uint4*)(gv + base + 32 + d4 * 8);
            uint32_t* dst = &vp_s[h2 * (16 * KP_STRIDE) + key2 * KP_STRIDE + d4 * 8];
            *(uint4*)dst = make_uint4(
                prmt(v0.x, v1.x, 0x5410), prmt(v0.x, v1.x, 0x7632),
                prmt(v0.y, v1.y, 0x5410), prmt(v0.y, v1.y, 0x7632));
            *(uint4*)(dst + 4) = make_uint4(
                prmt(v0.z, v1.z, 0x5410), prmt(v0.z, v1.z, 0x7632),
                prmt(v0.w, v1.w, 0x5410), prmt(v0.w, v1.w, 0x7632));
        }
        {
            int rr = tid >> 3, cc = (tid & 7) * 4;
            int4 rv = *(const int4*)&rp[((long)b * NN + row0 + rr) * NN + j0 + cc];
            rp_s[rr * 33 + cc + 0] = rv.x;
            rp_s[rr * 33 + cc + 1] = rv.y;
            rp_s[rr * 33 + cc + 2] = rv.z;
            rp_s[rr * 33 + cc + 3] = rv.w;
        }
        __syncthreads();

        float c[2][4][4];
        #pragma unroll
        for (int mt = 0; mt < 2; mt++)
            #pragma unroll
            for (int nt = 0; nt < 4; nt++)
                #pragma unroll
                for (int r = 0; r < 4; r++) c[mt][nt][r] = 0.f;

        #pragma unroll
        for (int nt = 0; nt < 4; nt++)
            #pragma unroll
            for (int ks = 0; ks < 2; ks++) {
                uint32_t bf[2];
                bf[0] = kh[(ks * 8 + t) * KP_STRIDE + nt * 8 + g];
                bf[1] = kh[(ks * 8 + t + 4) * KP_STRIDE + nt * 8 + g];
                mma_f16(c[0][nt], qa[0][ks], bf);
                mma_f16(c[1][nt], qa[1][ks], bf);
            }

        #pragma unroll
        for (int mt = 0; mt < 2; mt++) {
            int rA = mt * 16 + g;
            int rB = rA + 8;
            float mx0 = -1e30f, mx1 = -1e30f;
            #pragma unroll
            for (int nt = 0; nt < 4; nt++) {
                int colb = nt * 8 + 2 * t;
                int r00 = rp_s[rA * 33 + colb], r01 = rp_s[rA * 33 + colb + 1];
                int r10 = rp_s[rB * 33 + colb], r11 = rp_s[rB * 33 + colb + 1];
                c[mt][nt][0] += __shfl_sync(0xffffffffu, bt2, r00);
                c[mt][nt][1] += __shfl_sync(0xffffffffu, bt2, r01);
                c[mt][nt][2] += __shfl_sync(0xffffffffu, bt2, r10);
                c[mt][nt][3] += __shfl_sync(0xffffffffu, bt2, r11);
                mx0 = fmaxf(mx0, fmaxf(c[mt][nt][0], c[mt][nt][1]));
                mx1 = fmaxf(mx1, fmaxf(c[mt][nt][2], c[mt][nt][3]));
            }
            mx0 = fmaxf(mx0, __shfl_xor_sync(0xffffffffu, mx0, 1));
            mx0 = fmaxf(mx0, __shfl_xor_sync(0xffffffffu, mx0, 2));
            mx1 = fmaxf(mx1, __shfl_xor_sync(0xffffffffu, mx1, 1));
            mx1 = fmaxf(mx1, __shfl_xor_sync(0xffffffffu, mx1, 2));

            float nm0 = fmaxf(mrow[mt][0], mx0);
            float nm1 = fmaxf(mrow[mt][1], mx1);
            float corr0 = __expf(mrow[mt][0] - nm0);
            float corr1 = __expf(mrow[mt][1] - nm1);
            float rs0 = 0.f, rs1 = 0.f;
            #pragma unroll
            for (int nt = 0; nt < 4; nt++) {
                c[mt][nt][0] = __expf(c[mt][nt][0] - nm0);
                c[mt][nt][1] = __expf(c[mt][nt][1] - nm0);
                c[mt][nt][2] = __expf(c[mt][nt][2] - nm1);
                c[mt][nt][3] = __expf(c[mt][nt][3] - nm1);
                rs0 += c[mt][nt][0] + c[mt][nt][1];
                rs1 += c[mt][nt][2] + c[mt][nt][3];
            }
            rs0 += __shfl_xor_sync(0xffffffffu, rs0, 1);
            rs0 += __shfl_xor_sync(0xffffffffu, rs0, 2);
            rs1 += __shfl_xor_sync(0xffffffffu, rs1, 1);
            rs1 += __shfl_xor_sync(0xffffffffu, rs1, 2);
            lrow[mt][0] = lrow[mt][0] * corr0 + rs0;
            lrow[mt][1] = lrow[mt][1] * corr1 + rs1;
            #pragma unroll
            for (int nt = 0; nt < 4; nt++) {
                o[mt][nt][0] *= corr0; o[mt][nt][1] *= corr0;
                o[mt][nt][2] *= corr1; o[mt][nt][3] *= corr1;
            }
            mrow[mt][0] = nm0;
            mrow[mt][1] = nm1;
        }

        uint32_t pa[2][2][4];
        #pragma unroll
        for (int mt = 0; mt < 2; mt++)
            #pragma unroll
            for (int ks = 0; ks < 2; ks++) {
                pa[mt][ks][0] = h2pack(c[mt][2*ks  ][0], c[mt][2*ks  ][1]);
                pa[mt][ks][1] = h2pack(c[mt][2*ks  ][2], c[mt][2*ks  ][3]);
                pa[mt][ks][2] = h2pack(c[mt][2*ks+1][0], c[mt][2*ks+1][1]);
                pa[mt][ks][3] = h2pack(c[mt][2*ks+1][2], c[mt][2*ks+1][3]);
            }

        #pragma unroll
        for (int ks = 0; ks < 2; ks++)
            #pragma unroll
            for (int nt = 0; nt < 4; nt++) {
                uint32_t bf[2];
                bf[0] = vh[(ks * 8 + t) * KP_STRIDE + nt * 8 + g];
                bf[1] = vh[(ks * 8 + t + 4) * KP_STRIDE + nt * 8 + g];
                mma_f16(o[0][nt], pa[0][ks], bf);
                mma_f16(o[1][nt], pa[1][ks], bf);
            }
    }

    // epilogue: normalize, store fp16 to g_xh (A-matrix layout for proj GEMM)
    #pragma unroll
    for (int mt = 0; mt < 2; mt++) {
        float i0 = 1.f / lrow[mt][0];
        float i1 = 1.f / lrow[mt][1];
        int rA = row0 + mt * 16 + g;
        #pragma unroll
        for (int nt = 0; nt < 4; nt++) {
            int col = h * HD + nt * 8 + 2 * t;
            *(__half2*)&g_xh[((long)b * NN + rA) * CC + col] =
                __floats2half2_rn(o[mt][nt][0] * i0, o[mt][nt][1] * i0);
            *(__half2*)&g_xh[((long)b * NN + rA + 8) * CC + col] =
                __floats2half2_rn(o[mt][nt][2] * i1, o[mt][nt][3] * i1);
        }
    }
}

// ---------------------------------------------------------------------------
extern "C" void kernel_launch(void* const* d_in, const int* in_sizes, int n_in,
                              void* d_out, int out_size)
{
    const float* X       = (const float*)d_in[0];
    const int*   rp      = (const int*)  d_in[1];
    const int*   rel_len = (const int*)  d_in[2];
    const float* Wqkv    = (const float*)d_in[3];
    const float* Wproj   = (const float*)d_in[4];
    const float* bproj   = (const float*)d_in[5];
    const float* btab    = (const float*)d_in[6];
    float* out = (float*)d_out;

    __half* d_ah;   cudaGetSymbolAddress((void**)&d_ah,  g_ah);
    __half* d_wqt;  cudaGetSymbolAddress((void**)&d_wqt, g_wqt);
    __half* d_wpt;  cudaGetSymbolAddress((void**)&d_wpt, g_wpt);

    const int gemm_smem = 2 * GS_BUF * 16;   // 73728 B

    // converts
    convert_x_kernel<<<1024, 256>>>((const float4*)X, (uint4*)d_ah);
    transpose_w_kernel<<<dim3(24, 8), 256>>>(Wqkv,  d_wqt, 768);
    transpose_w_kernel<<<dim3(8, 8),  256>>>(Wproj, d_wpt, 256);

    // qkv GEMM (fp16 MMA)
    cudaFuncSetAttribute(gemm_f16_kernel<false>,
                         cudaFuncAttributeMaxDynamicSharedMemorySize, gemm_smem);
    gemm_f16_kernel<false><<<dim3(6, 64), 256, gemm_smem>>>(
        (const uint4*)d_ah, (const uint4*)d_wqt, nullptr, nullptr);

    // attention
    {
        const int smem_bytes = (8*16*KP_STRIDE * 2) * 4 + 32*33*4;
        cudaFuncSetAttribute(attn_mma_kernel,
                             cudaFuncAttributeMaxDynamicSharedMemorySize, smem_bytes);
        attn_mma_kernel<<<BB * 32, 256, smem_bytes>>>(rp, rel_len, btab);
    }

    // proj GEMM (fp16 MMA) + bias -> fp32 out
    cudaFuncSetAttribute(gemm_f16_kernel<true>,
                         cudaFuncAttributeMaxDynamicSharedMemorySize, gemm_smem);
    __half* d_xh;  cudaGetSymbolAddress((void**)&d_xh, g_xh);
    gemm_f16_kernel<true><<<dim3(2, 64), 256, gemm_smem>>>(
        (const uint4*)d_xh, (const uint4*)d_wpt, out, bproj);
}